// round 16
// baseline (speedup 1.0000x reference)
#include <cuda_runtime.h>
#include <cuda_bf16.h>
#include <cstdint>

#define B_   128
#define T_   512
#define D_   256
#define H_   512
#define G_   2048
#define K0_  768
#define K1_  1024
#define NKT0 (K0_ / 16)      // 48 ktiles
#define NKT1 (K1_ / 16)      // 64 ktiles
#define NCTA 128
#define NTHR 512
#define BH   (B_ * H_)

// dynamic smem layout (u32 indices): part0 | part1 | bounce(both) | W0 | W1
#define OFF_PART1  8448                  // 64 blocks * 132 floats
#define OFF_BOUNCE 16896
#define OFF_W0     17920
#define OFF_W1     (17920 + 12288)       // 30208
#define SMEM_U32   (30208 + 16384)       // 46592 -> 186368 B

// ---------------- persistent device scratch -----------------------------------
// Weight fragments: [ntg(256)][ktp][s=hi/lo][lane(32)][8 bf16]  (ktile pairs)
__device__ uint4 g_Wf0[(size_t)256 * NKT0 * 2 * 16];   // 6 MB
__device__ uint4 g_Wf1[(size_t)256 * NKT1 * 2 * 16];   // 8 MB
__device__ float g_b0[G_];
__device__ float g_b1[G_];
// Activations, PRE-SPLIT fragment order: per ktile block = [mg8(8)][s=hi/lo(2)][lane(32)] uint4
__device__ uint4 g_xf[(size_t)T_ * 16 * 512];          // 64 MB
__device__ uint4 g_h0f[2][32 * 512];
__device__ uint4 g_h1f[2][32 * 512];
__device__ unsigned g_count;
__device__ unsigned g_release;

// ---------------- helpers -------------------------------------------------------
__device__ __forceinline__ float sigm(float v) {
    return __fdividef(1.f, 1.f + __expf(-v));
}
__device__ __forceinline__ float ftanh(float x) {
    float e = __expf(-2.f * fabsf(x));
    float t = __fdividef(1.f - e, 1.f + e);
    return copysignf(t, x);
}

__device__ __forceinline__ uint32_t pack_split(float v) {
    __nv_bfloat16 h = __float2bfloat16(v);
    __nv_bfloat16 l = __float2bfloat16(v - __bfloat162float(h));
    return (uint32_t)__bfloat16_as_ushort(h) |
           ((uint32_t)__bfloat16_as_ushort(l) << 16);
}

__device__ __forceinline__ uint32_t prmt(uint32_t a, uint32_t b, uint32_t c) {
    uint32_t r;
    asm("prmt.b32 %0, %1, %2, %3;" : "=r"(r) : "r"(a), "r"(b), "r"(c));
    return r;
}

__device__ __forceinline__ void mma16816(float* d, const uint32_t* a, uint2 b) {
    asm volatile(
        "mma.sync.aligned.m16n8k16.row.col.f32.bf16.bf16.f32 "
        "{%0,%1,%2,%3}, {%4,%5,%6,%7}, {%8,%9}, {%0,%1,%2,%3};"
        : "+f"(d[0]), "+f"(d[1]), "+f"(d[2]), "+f"(d[3])
        : "r"(a[0]), "r"(a[1]), "r"(a[2]), "r"(a[3]), "r"(b.x), "r"(b.y));
}

__device__ __forceinline__ void gridBarrier(unsigned target) {
    __syncthreads();
    if (threadIdx.x == 0) {
        __threadfence();
        unsigned t = atomicAdd(&g_count, 1u);
        if (t == (unsigned)(NCTA - 1)) {
            g_count = 0;
            __threadfence();
            atomicAdd(&g_release, 1u);
        } else {
            while ((int)(*(volatile unsigned*)&g_release - target) < 0) {}
        }
        __threadfence();
    }
    __syncthreads();
}

// bf16-split store of W[np][k] into ktile-pair fragment layout (hi plane s=0, lo s=1)
__device__ __forceinline__ void wf_store(__nv_bfloat16* base, int NKTP,
                                         int np, int k, float v) {
    __nv_bfloat16 h = __float2bfloat16(v);
    __nv_bfloat16 l = __float2bfloat16(v - __bfloat162float(h));
    int ntg = np >> 3;
    int ln = ((np & 7) << 2) | ((k >> 1) & 3);
    int kt = k >> 4, ktp = kt >> 1, kh = kt & 1;
    int b = (k >> 3) & 1, e = k & 1;
    size_t o = ((((size_t)ntg * NKTP + ktp) * 2) * 32 + ln) * 8 + kh * 4 + b * 2 + e;
    base[o] = h;
    base[o + 256] = l;   // lo plane: +32 uint4
}

// ---------------- prep kernels ---------------------------------------------------
__global__ void prep_x(const float* __restrict__ x) {
    __shared__ float sx[16 * 256];
    int blk = blockIdx.x;           // t*8 + mg8
    int t = blk >> 3, mg = blk & 7;
    int tid = threadIdx.x;
    for (int i = tid; i < 16 * 256; i += 256) {
        int r = i >> 8, d = i & 255;
        sx[i] = x[(size_t)(mg * 16 + r) * T_ * D_ + (size_t)t * D_ + d];
    }
    __syncthreads();
    uint4* out = g_xf + (size_t)t * 16 * 512;
    for (int i = tid; i < 512; i += 256) {
        int kt = i >> 5, lane = i & 31;
        uint32_t hi[4], lo[4];
#pragma unroll
        for (int j = 0; j < 4; ++j) {
            int r = (lane >> 2) + (j & 1) * 8;
            int d0 = kt * 16 + (j >> 1) * 8 + ((lane & 3) << 1);
            uint32_t p0 = pack_split(sx[r * 256 + d0]);
            uint32_t p1 = pack_split(sx[r * 256 + d0 + 1]);
            hi[j] = prmt(p0, p1, 0x5410);
            lo[j] = prmt(p0, p1, 0x7632);
        }
        out[(size_t)kt * 512 + mg * 64 + lane] =
            make_uint4(hi[0], hi[1], hi[2], hi[3]);
        out[(size_t)kt * 512 + mg * 64 + 32 + lane] =
            make_uint4(lo[0], lo[1], lo[2], lo[3]);
    }
}

__global__ void prep_w0(const float* __restrict__ wx0, const float* __restrict__ projw,
                        const float* __restrict__ projb, const float* __restrict__ bx0,
                        const float* __restrict__ bh0) {
    int np = blockIdx.x;
    int jcol = np >> 2, q = np & 3;
    int n = q * H_ + jcol;
    int d = threadIdx.x;
    const float* wrow = wx0 + (size_t)n * D_;
    float acc = 0.f;
    for (int j = 0; j < D_; ++j) acc += wrow[j] * projw[(size_t)j * D_ + d];
    wf_store((__nv_bfloat16*)g_Wf0, NKT0 / 2, np, d, acc);
    if (d == 0) {
        float bb = bx0[n] + bh0[n];
        for (int j = 0; j < D_; ++j) bb += wrow[j] * projb[j];
        g_b0[np] = bb;
    }
}

__global__ void prep_rest(const float* __restrict__ wh0, const float* __restrict__ wx1,
                          const float* __restrict__ wh1, const float* __restrict__ bx1,
                          const float* __restrict__ bh1) {
    const int total = G_ * H_ + G_ * K1_ + G_;
    for (int i = blockIdx.x * blockDim.x + threadIdx.x; i < total;
         i += gridDim.x * blockDim.x) {
        if (i < G_ * H_) {
            int np = i / H_, k = i % H_;
            int n = (np & 3) * H_ + (np >> 2);
            wf_store((__nv_bfloat16*)g_Wf0, NKT0 / 2, np, D_ + k,
                     wh0[(size_t)n * H_ + k]);
        } else if (i < G_ * H_ + G_ * K1_) {
            int r = i - G_ * H_;
            int np = r / K1_, k = r % K1_;
            int n = (np & 3) * H_ + (np >> 2);
            float v = (k < H_) ? wx1[(size_t)n * H_ + k]
                               : wh1[(size_t)n * H_ + (k - H_)];
            wf_store((__nv_bfloat16*)g_Wf1, NKT1 / 2, np, k, v);
        } else {
            int np = i - G_ * H_ - G_ * K1_;
            int n = (np & 3) * H_ + (np >> 2);
            g_b1[np] = bx1[n] + bh1[n];
        }
    }
}

// ---------------- one GEMM tile: M=32/warp x N=16/CTA, 4-way K-split -------------
template <int NKT>
__device__ __forceinline__ void gemm_tile(const uint4* __restrict__ sW4,
    const uint4* __restrict__ pA, const uint4* __restrict__ pB, int split,
    int mg, int kgrp, int lane, float acc[2][2][4]) {
    constexpr int NKTP = NKT / 2;
    constexpr int NKTH = NKT / 4;
    const int ktbase = kgrp * NKTH;

#pragma unroll
    for (int mt = 0; mt < 2; ++mt)
#pragma unroll
        for (int nt = 0; nt < 2; ++nt)
#pragma unroll
            for (int e = 0; e < 4; ++e) acc[mt][nt][e] = 0.f;

    uint4 ab[2][4];   // 2-ktile ring x [mt*2 + plane]
#pragma unroll
    for (int p = 0; p < 2; ++p) {
        int kt = ktbase + p;
        const uint4* base = (kt < split) ? pA + (size_t)kt * 512
                                         : pB + (size_t)(kt - split) * 512;
#pragma unroll
        for (int mt = 0; mt < 2; ++mt) {
            const uint4* s = base + (2 * mg + mt) * 64 + lane;
            ab[p][mt * 2 + 0] = s[0];
            ab[p][mt * 2 + 1] = s[32];
        }
    }
    uint4 bh[2], bl[2];

#pragma unroll 2
    for (int kk = 0; kk < NKTH; ++kk) {
        int ktg = ktbase + kk;
        int half = kk & 1;               // ktbase even (NKTH = 12 or 16)
        if (half == 0) {
            int ktp = ktg >> 1;
#pragma unroll
            for (int nt = 0; nt < 2; ++nt) {
                const uint4* wp = sW4 + (size_t)((nt * NKTP + ktp) * 2) * 32 + lane;
                bh[nt] = wp[0];
                bl[nt] = wp[32];
            }
        }
        uint4* cur = ab[kk & 1];
        // pass 1: hi·hi
#pragma unroll
        for (int mt = 0; mt < 2; ++mt)
#pragma unroll
            for (int nt = 0; nt < 2; ++nt) {
                uint2 b2 = half ? make_uint2(bh[nt].z, bh[nt].w)
                                : make_uint2(bh[nt].x, bh[nt].y);
                mma16816(acc[mt][nt], (const uint32_t*)&cur[mt * 2 + 0], b2);
            }
        // pass 2: lo·hi
#pragma unroll
        for (int mt = 0; mt < 2; ++mt)
#pragma unroll
            for (int nt = 0; nt < 2; ++nt) {
                uint2 b2 = half ? make_uint2(bh[nt].z, bh[nt].w)
                                : make_uint2(bh[nt].x, bh[nt].y);
                mma16816(acc[mt][nt], (const uint32_t*)&cur[mt * 2 + 1], b2);
            }
        // pass 3: hi·lo
#pragma unroll
        for (int mt = 0; mt < 2; ++mt)
#pragma unroll
            for (int nt = 0; nt < 2; ++nt) {
                uint2 b2 = half ? make_uint2(bl[nt].z, bl[nt].w)
                                : make_uint2(bl[nt].x, bl[nt].y);
                mma16816(acc[mt][nt], (const uint32_t*)&cur[mt * 2 + 0], b2);
            }
        if (kk + 2 < NKTH) {
            int kn = ktg + 2;
            const uint4* base = (kn < split) ? pA + (size_t)kn * 512
                                             : pB + (size_t)(kn - split) * 512;
#pragma unroll
            for (int mt = 0; mt < 2; ++mt) {
                const uint4* s = base + (2 * mg + mt) * 64 + lane;
                cur[mt * 2 + 0] = s[0];
                cur[mt * 2 + 1] = s[32];
            }
        }
    }
}

__device__ __forceinline__ void deposit(float* __restrict__ partL,
                                        int mg, int kgrp, int lane,
                                        float acc[2][2][4]) {
#pragma unroll
    for (int mt = 0; mt < 2; ++mt)
#pragma unroll
        for (int nt = 0; nt < 2; ++nt) {
            int blk = ((kgrp * 4 + mg) * 2 + mt) * 2 + nt;
            *(float4*)(partL + blk * 132 + lane * 4) =
                make_float4(acc[mt][nt][0], acc[mt][nt][1],
                            acc[mt][nt][2], acc[mt][nt][3]);
        }
}

// ---------------- persistent main kernel -----------------------------------------
// 128 uniform CTAs, each owns 16 gate-cols (4 h-cols) of BOTH layers.
__global__ void __launch_bounds__(NTHR, 1) lstm_main() {
    extern __shared__ uint32_t smw[];
    __shared__ float sb0[16], sb1[16];
    float* part0 = (float*)smw;
    float* part1 = (float*)(smw + OFF_PART1);
    uint32_t* bounce = smw + OFF_BOUNCE;       // [layer(2)][row(128)][jc(4)]
    const uint4* sW0 = (const uint4*)(smw + OFF_W0);
    const uint4* sW1 = (const uint4*)(smw + OFF_W1);

    const int cta = blockIdx.x, tid = threadIdx.x;
    const int lc = cta;
    const int lane = tid & 31, w = tid >> 5;
    const int mg = w & 3, kgrp = w >> 2;

    // load resident weight slices (2 ntg blocks per layer, contiguous)
    {
        const uint4* s0 = g_Wf0 + (size_t)lc * 3072;   // 2 * (NKT0/2) * 2 * 32
        const uint4* s1 = g_Wf1 + (size_t)lc * 4096;
        uint4* d0 = (uint4*)(smw + OFF_W0);
        uint4* d1 = (uint4*)(smw + OFF_W1);
        for (int i = tid; i < 3072; i += NTHR) d0[i] = s0[i];
        for (int i = tid; i < 4096; i += NTHR) d1[i] = s1[i];
        if (tid < 16) sb0[tid] = g_b0[lc * 16 + tid];
        else if (tid < 32) sb1[tid - 16] = g_b1[lc * 16 + tid - 16];
    }
    // zero h fragment buffers each launch (deterministic)
    {
        uint32_t* hz0 = (uint32_t*)g_h0f;
        uint32_t* hz1 = (uint32_t*)g_h1f;
        for (int i = cta * NTHR + tid; i < 2 * 32 * 512 * 4; i += NCTA * NTHR) {
            hz0[i] = 0u;
            hz1[i] = 0u;
        }
    }

    unsigned relBase = *(volatile unsigned*)&g_release;
    unsigned gen = 0;
    float cst[2] = {0.f, 0.f};     // one cell per thread per layer

    // epilogue index precompute (invariant across phases)
    const int erow = tid >> 2, ejc = tid & 3;
    const int emg = erow >> 5, erw = erow & 31;
    const int emt = (erw >> 4) & 1, erp = (erw >> 3) & 1, erlo = erw & 7;
    const int ent = ejc >> 1, ec2 = ejc & 1;
    const int eoff = (((emg * 2 + emt) * 2 + ent)) * 132 + erlo * 16 + erp * 2;
    // store index precompute
    const int su = tid & 255, slayer = tid >> 8;
    const int srow = su >> 1, spp = su & 1;
    const int skt = lc >> 2, shalf = (lc >> 1) & 1, spr = (lc & 1) * 2 + spp;
    const int smg = srow >> 4, sr16 = srow & 15;
    const int slane = (sr16 & 7) * 4 + spr;
    const int sj = shalf * 2 + (sr16 >> 3);
    const size_t sidx = ((size_t)skt * 512 + smg * 64 + slane) * 4 + sj;

    gridBarrier(relBase + ++gen);

    for (int phase = 0; phase <= T_; ++phase) {
        const bool do0 = (phase < T_), do1 = (phase >= 1);
        float acc[2][2][4];
        if (do0) {
            int t = phase;
            gemm_tile<NKT0>(sW0, g_xf + (size_t)t * 16 * 512,
                            g_h0f[(t & 1) ^ 1], 16, mg, kgrp, lane, acc);
            deposit(part0, mg, kgrp, lane, acc);
        }
        if (do1) {
            int t = phase - 1;
            gemm_tile<NKT1>(sW1, g_h0f[t & 1],
                            g_h1f[(t & 1) ^ 1], 32, mg, kgrp, lane, acc);
            deposit(part1, mg, kgrp, lane, acc);
        }
        __syncthreads();

        // distributed epilogue: 1 cell / thread / layer
#pragma unroll
        for (int L = 0; L < 2; ++L) {
            if (L == 0 ? !do0 : !do1) continue;
            const float* partL = L ? part1 : part0;
            const float* sb = L ? sb1 : sb0;
            float g4[4] = {0.f, 0.f, 0.f, 0.f};
#pragma unroll
            for (int kg = 0; kg < 4; ++kg) {
                const float* bp = partL + kg * 16 * 132 + eoff;
                float2 v0 = *(const float2*)(bp + (ec2 * 2) * 4);
                float2 v1 = *(const float2*)(bp + (ec2 * 2 + 1) * 4);
                g4[0] += v0.x; g4[1] += v0.y;
                g4[2] += v1.x; g4[3] += v1.y;
            }
            float iv = g4[0] + sb[ejc * 4 + 0];
            float fv = g4[1] + sb[ejc * 4 + 1];
            float gv = g4[2] + sb[ejc * 4 + 2];
            float ov = g4[3] + sb[ejc * 4 + 3];
            float cn = sigm(fv) * cst[L] + sigm(iv) * ftanh(gv);
            cst[L] = cn;
            bounce[L * 512 + erow * 4 + ejc] = pack_split(sigm(ov) * ftanh(cn));
        }
        __syncthreads();

        // pre-split h fragment store (quarter-ktile per CTA per layer)
        {
            const bool act = slayer ? do1 : do0;
            if (act) {
                const uint32_t* bL = bounce + slayer * 512;
                uint32_t c0 = bL[srow * 4 + spp * 2];
                uint32_t c1 = bL[srow * 4 + spp * 2 + 1];
                uint32_t hiv = prmt(c0, c1, 0x5410);
                uint32_t lov = prmt(c0, c1, 0x7632);
                uint32_t* o = slayer
                    ? (uint32_t*)g_h1f[(phase - 1) & 1]
                    : (uint32_t*)g_h0f[phase & 1];
                o[sidx] = hiv;
                o[sidx + 128] = lov;   // lo plane: +32 uint4 = +128 u32
            }
        }
        gridBarrier(relBase + ++gen);
    }
}

// ---------------- FC head ----------------------------------------------------------
__global__ void fc_head(const float* __restrict__ fc1w, const float* __restrict__ fc1b,
                        const float* __restrict__ fc2w, const float* __restrict__ fc2b,
                        float* __restrict__ out) {
    __shared__ float hsh[H_];
    __shared__ float hid[32];
    int b = blockIdx.x, tid = threadIdx.x;
    const uint32_t* hf = (const uint32_t*)g_h1f[1];   // last t=511 odd -> buf1
#pragma unroll
    for (int rr = 0; rr < 2; ++rr) {
        int col = tid + rr * 256;
        int kt = col >> 4, k16 = col & 15;
        int half = k16 >> 3, q = (k16 >> 1) & 3, e = k16 & 1;
        int r = b & 15, mg = b >> 4;
        int lane2 = ((r & 7) << 2) | q;
        int j = half * 2 + ((r >> 3) & 1);
        size_t u32i = ((size_t)kt * 512 + mg * 64 + lane2) * 4 + j;
        uint32_t uh = hf[u32i];
        uint32_t ul = hf[u32i + 128];
        unsigned short sh = e ? (unsigned short)(uh >> 16) : (unsigned short)(uh & 0xFFFFu);
        unsigned short sl = e ? (unsigned short)(ul >> 16) : (unsigned short)(ul & 0xFFFFu);
        hsh[col] = __bfloat162float(__ushort_as_bfloat16(sh)) +
                   __bfloat162float(__ushort_as_bfloat16(sl));
    }
    __syncthreads();
    int w = tid >> 5, lane = tid & 31;
    for (int j = w; j < 32; j += 8) {
        const float* wr = fc1w + (size_t)j * H_;
        float s = 0.f;
        for (int k = lane; k < H_; k += 32) s += hsh[k] * wr[k];
#pragma unroll
        for (int off = 16; off; off >>= 1) s += __shfl_xor_sync(0xffffffffu, s, off);
        if (lane == 0) hid[j] = fmaxf(s + fc1b[j], 0.f) * fc2w[j];
    }
    __syncthreads();
    if (tid < 32) {
        float v = hid[tid];
#pragma unroll
        for (int off = 16; off; off >>= 1) v += __shfl_xor_sync(0xffffffffu, v, off);
        if (tid == 0) out[b] = v + fc2b[0];
    }
}

// ---------------- launch -------------------------------------------------------------
extern "C" void kernel_launch(void* const* d_in, const int* in_sizes, int n_in,
                              void* d_out, int out_size) {
    const float* x     = (const float*)d_in[0];
    const float* projw = (const float*)d_in[1];
    const float* projb = (const float*)d_in[2];
    const float* wx0   = (const float*)d_in[3];
    const float* bx0   = (const float*)d_in[4];
    const float* wh0   = (const float*)d_in[5];
    const float* bh0   = (const float*)d_in[6];
    const float* wx1   = (const float*)d_in[7];
    const float* bx1   = (const float*)d_in[8];
    const float* wh1   = (const float*)d_in[9];
    const float* bh1   = (const float*)d_in[10];
    const float* fc1w  = (const float*)d_in[11];
    const float* fc1b  = (const float*)d_in[12];
    const float* fc2w  = (const float*)d_in[13];
    const float* fc2b  = (const float*)d_in[14];
    float* out = (float*)d_out;

    const int SMEM_BYTES = SMEM_U32 * 4;   // 186368
    cudaFuncSetAttribute(lstm_main, cudaFuncAttributeMaxDynamicSharedMemorySize,
                         SMEM_BYTES);

    prep_x<<<T_ * 8, 256>>>(x);
    prep_w0<<<G_, D_>>>(wx0, projw, projb, bx0, bh0);
    prep_rest<<<2048, 256>>>(wh0, wx1, wh1, bx1, bh1);
    lstm_main<<<NCTA, NTHR, SMEM_BYTES>>>();
    fc_head<<<B_, 256>>>(fc1w, fc1b, fc2w, fc2b, out);
}